// round 11
// baseline (speedup 1.0000x reference)
#include <cuda_runtime.h>
#include <cuda_fp16.h>
#include <cstdint>

#define NMAX 50000
#define EMAX 800000
#define H 128

// ---------------- scratch (__device__ globals) ------------------------------
__device__ uint2  g_nbh[NMAX * 32];        // node_embedding as fp16 (256B/row)
__device__ float  g_s[NMAX];               // per-node sum of edge_attr
__device__ float4 g_v3[H / 4];             // relu(W4) @ W3
__device__ int    g_cnt[NMAX + 4];         // degree counts (padded to int4)
__device__ int    g_cur[NMAX];             // fill cursors
__device__ int    g_off[NMAX + 1];         // CSR row offsets
__device__ int    g_cols[EMAX];            // CSR column indices

// ---------------------------------------------------------------------------
__device__ __forceinline__ unsigned f2tf32(float f) {
    unsigned u;
    asm("cvt.rna.tf32.f32 %0, %1;" : "=r"(u) : "f"(f));
    return u;
}

__device__ __forceinline__ void mma_tf32(float* c, const unsigned* a,
                                         const unsigned* b) {
    asm volatile(
        "mma.sync.aligned.m16n8k8.row.col.f32.tf32.tf32.f32 "
        "{%0,%1,%2,%3}, {%4,%5,%6,%7}, {%8,%9}, {%0,%1,%2,%3};"
        : "+f"(c[0]), "+f"(c[1]), "+f"(c[2]), "+f"(c[3])
        : "r"(a[0]), "r"(a[1]), "r"(a[2]), "r"(a[3]), "r"(b[0]), "r"(b[1]));
}

__device__ __forceinline__ void load_edge(const void* __restrict__ ei, int e,
                                          int idx, int& r, int& c) {
    const int* p32 = (const int*)ei;
    bool is64 = (p32[1] | p32[3] | p32[5] | p32[7]) == 0;  // int64 => odd words 0
    if (is64) {
        const long long* p64 = (const long long*)ei;
        r = (int)p64[idx];
        c = (int)p64[e + idx];
    } else {
        r = p32[idx];
        c = p32[e + idx];
    }
}

// ---------------------------------------------------------------------------
// Prep: zero cnt/s, convert nb -> fp16 table, v3 = relu(W4)@W3 (block 0).
// ---------------------------------------------------------------------------
__global__ void prep_kernel(const float* __restrict__ nb,
                            const float* __restrict__ W4,
                            const float* __restrict__ W3, int n) {
    int i = blockIdx.x * blockDim.x + threadIdx.x;
    int npad = (n + 3) & ~3;
    if (i < npad) g_cnt[i] = 0;
    if (i < n) g_s[i] = 0.f;
    if (i < n * 32) {
        float4 v = ((const float4*)nb)[i];
        __half2 h0 = __floats2half2_rn(v.x, v.y);
        __half2 h1 = __floats2half2_rn(v.z, v.w);
        uint2 u;
        u.x = *(unsigned*)&h0;
        u.y = *(unsigned*)&h1;
        g_nbh[i] = u;
    }
    if (blockIdx.x == 0 && threadIdx.x < H) {
        int j = threadIdx.x;
        float acc = 0.f;
#pragma unroll 8
        for (int c = 0; c < H; ++c) {
            float w = W4[c];
            w = w > 0.f ? w : 0.f;
            acc += w * W3[c * H + j];
        }
        ((float*)g_v3)[j] = acc;
    }
}

// ---------------------------------------------------------------------------
__global__ void hist_kernel(const void* __restrict__ ei,
                            const float* __restrict__ ea, int e, int n) {
    int i = blockIdx.x * blockDim.x + threadIdx.x;
    if (i >= e) return;
    int r, c;
    load_edge(ei, e, i, r, c);
    if ((unsigned)r < (unsigned)n) {
        atomicAdd(&g_cnt[r], 1);
        atomicAdd(&g_s[r], ea[i]);
    }
}

// ---------------------------------------------------------------------------
// Single-pass scan: block b sums g_cnt[0 .. 1024b) for its base (redundant,
// L2-cached), then locally scans its 1024-count chunk. Cursors -> g_cur.
// ---------------------------------------------------------------------------
__global__ void scan_kernel(int n, int n4, int nbs) {
    __shared__ int red[8];
    __shared__ int ts[256];
    __shared__ int sbase;
    int t = threadIdx.x;
    int b = blockIdx.x;
    int lane = t & 31, wid = t >> 5;

    int s = 0;
    int lim = b * 256;   // int4 units
    for (int i = t; i < lim; i += 256) {
        int4 v = ((const int4*)g_cnt)[i];
        s += v.x + v.y + v.z + v.w;
    }
#pragma unroll
    for (int o = 16; o > 0; o >>= 1) s += __shfl_down_sync(0xffffffffu, s, o);
    if (lane == 0) red[wid] = s;
    __syncthreads();
    if (t == 0) {
        int a = 0;
#pragma unroll
        for (int k = 0; k < 8; ++k) a += red[k];
        sbase = a;
    }
    __syncthreads();
    int base = sbase;

    int i = b * 256 + t;
    int4 v = (i < n4) ? ((const int4*)g_cnt)[i] : make_int4(0, 0, 0, 0);
    int tot = v.x + v.y + v.z + v.w;
    ts[t] = tot;
    __syncthreads();
#pragma unroll
    for (int d = 1; d < 256; d <<= 1) {
        int xv = (t >= d) ? ts[t - d] : 0;
        __syncthreads();
        ts[t] += xv;
        __syncthreads();
    }
    if (i < n4) {
        int o0 = base + ts[t] - tot;
        int o1 = o0 + v.x, o2 = o1 + v.y, o3 = o2 + v.z;
        int4 offs = make_int4(o0, o1, o2, o3);
        ((int4*)g_off)[i] = offs;
        ((int4*)g_cur)[i] = offs;
    }
    if (b == nbs - 1 && t == 255) g_off[n] = base + ts[255];
}

// ---------------------------------------------------------------------------
__global__ void fill_kernel(const void* __restrict__ ei, int e, int n) {
    int i = blockIdx.x * blockDim.x + threadIdx.x;
    if (i >= e) return;
    int r, c;
    load_edge(ei, e, i, r, c);
    if ((unsigned)r >= (unsigned)n || (unsigned)c >= (unsigned)n) return;
    int pos = atomicAdd(&g_cur[r], 1);
    g_cols[pos] = c;
}

// ---------------------------------------------------------------------------
// Fused aggregate + tensor GEMM + epilogue.
// Phase A: warp-per-row CSR aggregation of fp16 nb rows -> tf32 As tile.
//   A' = [aggr(128) | x(8) | s(1) | 0..] (K=144 used), B' = [W2 ; W1 ; v3].
// Phase B: tf32 mma.sync, 128x128 tile, 8 warps (4M x 2N).
// Smem: As[128][148] tf32 (stride%32==20 -> conflict-free frags; 16B-aligned
// uint4 Phase-A stores), Bs[32][132] per k-chunk.
// ---------------------------------------------------------------------------
#define AS2 148
#define BS_STRIDE 132
#define SMEM_MMA ((128 * AS2 + 32 * BS_STRIDE) * 4)

__global__ void __launch_bounds__(256, 2)
mma_fused_kernel(const float* __restrict__ x,
                 const float* __restrict__ W1,
                 const float* __restrict__ W2,
                 float* __restrict__ out, int n) {
    extern __shared__ unsigned smu[];
    unsigned* As = smu;               // [128][AS2]
    unsigned* Bs = smu + 128 * AS2;   // [32][BS_STRIDE]

    const int t    = threadIdx.x;
    const int lane = t & 31;
    const int w    = t >> 5;
    const int rbase = blockIdx.x * 128;

    // ---- Phase A: x/s K-extension region (k = 128..143) --------------------
    for (int i = t; i < 128 * 16; i += 256) {
        int row = i >> 4, kk = i & 15;
        int r = rbase + row;
        float v = 0.f;
        if (r < n) {
            if (kk < 8)       v = x[r * 8 + kk];
            else if (kk == 8) v = g_s[r];
        }
        As[row * AS2 + 128 + kk] = f2tf32(v);
    }

    // ---- Phase A: CSR aggregation straight into As (k = 0..127) ------------
    for (int row = w; row < 128; row += 8) {
        int r = rbase + row;
        float4 acc = make_float4(0.f, 0.f, 0.f, 0.f);
        if (r < n) {
            int beg = g_off[r], end = g_off[r + 1];
            int j = beg;
            for (; j + 8 <= end; j += 8) {
                uint2 u[8];
#pragma unroll
                for (int q = 0; q < 8; ++q)
                    u[q] = g_nbh[g_cols[j + q] * 32 + lane];
#pragma unroll
                for (int q = 0; q < 8; ++q) {
                    float2 a = __half22float2(*(__half2*)&u[q].x);
                    float2 b = __half22float2(*(__half2*)&u[q].y);
                    acc.x += a.x; acc.y += a.y; acc.z += b.x; acc.w += b.y;
                }
            }
            for (; j < end; ++j) {
                uint2 u = g_nbh[g_cols[j] * 32 + lane];
                float2 a = __half22float2(*(__half2*)&u.x);
                float2 b = __half22float2(*(__half2*)&u.y);
                acc.x += a.x; acc.y += a.y; acc.z += b.x; acc.w += b.y;
            }
        }
        *(uint4*)&As[row * AS2 + 4 * lane] =
            make_uint4(f2tf32(acc.x), f2tf32(acc.y), f2tf32(acc.z), f2tf32(acc.w));
    }

    // ---- Phase B: MMA -------------------------------------------------------
    const int wr0 = (w >> 1) * 32;
    const int wc0 = (w & 1) * 64;
    const int gid = lane >> 2;
    const int tig = lane & 3;

    float acc[2][8][4];
#pragma unroll
    for (int mi = 0; mi < 2; ++mi)
#pragma unroll
        for (int ni = 0; ni < 8; ++ni)
#pragma unroll
            for (int q = 0; q < 4; ++q) acc[mi][ni][q] = 0.f;

    for (int chunk = 0; chunk < 5; ++chunk) {
        __syncthreads();   // As complete (1st iter) / Bs consumed (later iters)
        if (chunk < 4) {
            for (int i = t; i < 32 * 32; i += 256) {
                int kk = i >> 5, q = i & 31;
                float4 v = ((const float4*)W2)[(chunk * 32 + kk) * 32 + q];
                unsigned* p = &Bs[kk * BS_STRIDE + 4 * q];
                p[0] = f2tf32(v.x); p[1] = f2tf32(v.y);
                p[2] = f2tf32(v.z); p[3] = f2tf32(v.w);
            }
        } else {
            for (int i = t; i < 16 * 128; i += 256) {
                int kk = i >> 7, col = i & 127;
                float v = 0.f;
                if (kk < 8)       v = W1[kk * H + col];
                else if (kk == 8) v = ((const float*)g_v3)[col];
                Bs[kk * BS_STRIDE + col] = f2tf32(v);
            }
        }
        __syncthreads();

        const int ksteps = (chunk < 4) ? 4 : 2;
        for (int ks = 0; ks < ksteps; ++ks) {
            const int k0 = ks * 8;
            const int ka = chunk * 32 + k0;
            unsigned a[2][4], b[8][2];
#pragma unroll
            for (int mi = 0; mi < 2; ++mi) {
                int row = wr0 + mi * 16 + gid;
                a[mi][0] = As[row * AS2 + ka + tig];
                a[mi][1] = As[(row + 8) * AS2 + ka + tig];
                a[mi][2] = As[row * AS2 + ka + tig + 4];
                a[mi][3] = As[(row + 8) * AS2 + ka + tig + 4];
            }
#pragma unroll
            for (int ni = 0; ni < 8; ++ni) {
                int col = wc0 + ni * 8 + gid;
                b[ni][0] = Bs[(k0 + tig) * BS_STRIDE + col];
                b[ni][1] = Bs[(k0 + tig + 4) * BS_STRIDE + col];
            }
#pragma unroll
            for (int mi = 0; mi < 2; ++mi)
#pragma unroll
                for (int ni = 0; ni < 8; ++ni)
                    mma_tf32(acc[mi][ni], a[mi], b[ni]);
        }
    }

    // ---- epilogue: relu + store --------------------------------------------
#pragma unroll
    for (int mi = 0; mi < 2; ++mi) {
#pragma unroll
        for (int half = 0; half < 2; ++half) {
            int r = rbase + wr0 + mi * 16 + gid + half * 8;
            if (r >= n) continue;
#pragma unroll
            for (int ni = 0; ni < 8; ++ni) {
                int col = wc0 + ni * 8 + 2 * tig;
                float v0 = acc[mi][ni][half * 2 + 0];
                float v1 = acc[mi][ni][half * 2 + 1];
                v0 = v0 > 0.f ? v0 : 0.f;
                v1 = v1 > 0.f ? v1 : 0.f;
                ((float2*)out)[r * 64 + (col >> 1)] = make_float2(v0, v1);
            }
        }
    }
}

// ---------------------------------------------------------------------------
extern "C" void kernel_launch(void* const* d_in, const int* in_sizes, int n_in,
                              void* d_out, int out_size) {
    const float* x   = (const float*)d_in[0];
    const void*  ei  = d_in[1];                 // int32 or int64 (device-detected)
    const float* ea  = (const float*)d_in[2];
    const float* nb  = (const float*)d_in[3];
    const float* W1  = (const float*)d_in[4];
    const float* W2  = (const float*)d_in[5];
    const float* W3  = (const float*)d_in[6];
    const float* W4  = (const float*)d_in[7];
    float* out = (float*)d_out;

    const int n   = in_sizes[0] / 8;   // 50000
    const int e   = in_sizes[2];       // 800000
    const int n4  = (n + 3) / 4;       // 12500
    const int nbs = (n4 + 255) / 256;  // 49 scan chunks
    const int ntiles = (n + 127) / 128;

    cudaFuncSetAttribute(mma_fused_kernel,
                         cudaFuncAttributeMaxDynamicSharedMemorySize, SMEM_MMA);

    prep_kernel<<<(n * 32 + 255) / 256, 256>>>(nb, W4, W3, n);
    hist_kernel<<<(e + 255) / 256, 256>>>(ei, ea, e, n);
    scan_kernel<<<nbs, 256>>>(n, n4, nbs);
    fill_kernel<<<(e + 255) / 256, 256>>>(ei, e, n);
    mma_fused_kernel<<<ntiles, 256, SMEM_MMA>>>(x, W1, W2, out, n);
}

// round 12
// speedup vs baseline: 1.0501x; 1.0501x over previous
#include <cuda_runtime.h>
#include <cuda_fp16.h>
#include <cstdint>

#define NMAX 50000
#define EMAX 800000
#define H 128

// ---------------- scratch (__device__ globals) ------------------------------
__device__ float4 g_aggr[NMAX * (H / 4)];  // segment-sum of nb rows (fp32)
__device__ uint2  g_nbh[NMAX * 32];        // node_embedding as fp16 (256B/row)
__device__ float  g_s[NMAX];               // per-node sum of edge_attr
__device__ float4 g_v3[H / 4];             // relu(W4) @ W3
__device__ int    g_cnt[NMAX + 4];         // degree counts (padded to int4)
__device__ int    g_off[NMAX + 1];         // CSR row offsets
__device__ int    g_rank[EMAX];            // per-edge rank within its row
__device__ int    g_cols[EMAX];            // CSR column indices

// ---------------------------------------------------------------------------
__device__ __forceinline__ unsigned f2tf32(float f) {
    unsigned u;
    asm("cvt.rna.tf32.f32 %0, %1;" : "=r"(u) : "f"(f));
    return u;
}

__device__ __forceinline__ void mma_tf32(float* c, const unsigned* a,
                                         const unsigned* b) {
    asm volatile(
        "mma.sync.aligned.m16n8k8.row.col.f32.tf32.tf32.f32 "
        "{%0,%1,%2,%3}, {%4,%5,%6,%7}, {%8,%9}, {%0,%1,%2,%3};"
        : "+f"(c[0]), "+f"(c[1]), "+f"(c[2]), "+f"(c[3])
        : "r"(a[0]), "r"(a[1]), "r"(a[2]), "r"(a[3]), "r"(b[0]), "r"(b[1]));
}

__device__ __forceinline__ void load_edge(const void* __restrict__ ei, int e,
                                          int idx, int& r, int& c) {
    const int* p32 = (const int*)ei;
    bool is64 = (p32[1] | p32[3] | p32[5] | p32[7]) == 0;  // int64 => odd words 0
    if (is64) {
        const long long* p64 = (const long long*)ei;
        r = (int)p64[idx];
        c = (int)p64[e + idx];
    } else {
        r = p32[idx];
        c = p32[e + idx];
    }
}

// ---------------------------------------------------------------------------
// Prep: zero cnt/s, convert nb -> fp16 table, v3 = relu(W4)@W3 (block 0).
// ---------------------------------------------------------------------------
__global__ void prep_kernel(const float* __restrict__ nb,
                            const float* __restrict__ W4,
                            const float* __restrict__ W3, int n) {
    int i = blockIdx.x * blockDim.x + threadIdx.x;
    int npad = (n + 3) & ~3;
    if (i < npad) g_cnt[i] = 0;
    if (i < n) g_s[i] = 0.f;
    if (i < n * 32) {
        float4 v = ((const float4*)nb)[i];
        __half2 h0 = __floats2half2_rn(v.x, v.y);
        __half2 h1 = __floats2half2_rn(v.z, v.w);
        uint2 u;
        u.x = *(unsigned*)&h0;
        u.y = *(unsigned*)&h1;
        g_nbh[i] = u;
    }
    if (blockIdx.x == 0 && threadIdx.x < H) {
        int j = threadIdx.x;
        float acc = 0.f;
#pragma unroll 8
        for (int c = 0; c < H; ++c) {
            float w = W4[c];
            w = w > 0.f ? w : 0.f;
            acc += w * W3[c * H + j];
        }
        ((float*)g_v3)[j] = acc;
    }
}

// ---------------------------------------------------------------------------
// Histogram: degree counts (return value = per-edge rank), edge-attr sums.
// ---------------------------------------------------------------------------
__global__ void hist_kernel(const void* __restrict__ ei,
                            const float* __restrict__ ea, int e, int n) {
    int i = blockIdx.x * blockDim.x + threadIdx.x;
    if (i >= e) return;
    int r, c;
    load_edge(ei, e, i, r, c);
    if ((unsigned)r < (unsigned)n) {
        g_rank[i] = atomicAdd(&g_cnt[r], 1);
        atomicAdd(&g_s[r], ea[i]);
    }
}

// ---------------------------------------------------------------------------
// Single-pass scan: block b sums g_cnt[0 .. 1024b) for its base (redundant,
// L2-cached), then locally scans its 1024-count chunk.
// ---------------------------------------------------------------------------
__global__ void scan_kernel(int n, int n4, int nbs) {
    __shared__ int red[8];
    __shared__ int ts[256];
    __shared__ int sbase;
    int t = threadIdx.x;
    int b = blockIdx.x;
    int lane = t & 31, wid = t >> 5;

    int s = 0;
    int lim = b * 256;   // int4 units
    for (int i = t; i < lim; i += 256) {
        int4 v = ((const int4*)g_cnt)[i];
        s += v.x + v.y + v.z + v.w;
    }
#pragma unroll
    for (int o = 16; o > 0; o >>= 1) s += __shfl_down_sync(0xffffffffu, s, o);
    if (lane == 0) red[wid] = s;
    __syncthreads();
    if (t == 0) {
        int a = 0;
#pragma unroll
        for (int k = 0; k < 8; ++k) a += red[k];
        sbase = a;
    }
    __syncthreads();
    int base = sbase;

    int i = b * 256 + t;
    int4 v = (i < n4) ? ((const int4*)g_cnt)[i] : make_int4(0, 0, 0, 0);
    int tot = v.x + v.y + v.z + v.w;
    ts[t] = tot;
    __syncthreads();
#pragma unroll
    for (int d = 1; d < 256; d <<= 1) {
        int xv = (t >= d) ? ts[t - d] : 0;
        __syncthreads();
        ts[t] += xv;
        __syncthreads();
    }
    if (i < n4) {
        int o0 = base + ts[t] - tot;
        int o1 = o0 + v.x, o2 = o1 + v.y, o3 = o2 + v.z;
        ((int4*)g_off)[i] = make_int4(o0, o1, o2, o3);
    }
    if (b == nbs - 1 && t == 255) g_off[n] = base + ts[255];
}

// ---------------------------------------------------------------------------
// Fill: atomic-free — position = off[r] + rank[i].
// ---------------------------------------------------------------------------
__global__ void fill_kernel(const void* __restrict__ ei, int e, int n) {
    int i = blockIdx.x * blockDim.x + threadIdx.x;
    if (i >= e) return;
    int r, c;
    load_edge(ei, e, i, r, c);
    if ((unsigned)r >= (unsigned)n || (unsigned)c >= (unsigned)n) return;
    g_cols[g_off[r] + g_rank[i]] = c;
}

// ---------------------------------------------------------------------------
// Aggregate: warp per row, fp16 gathers (256B/row), fp32 accumulate.
// ---------------------------------------------------------------------------
__global__ void aggr_kernel(int n) {
    int w    = (blockIdx.x * blockDim.x + threadIdx.x) >> 5;
    int lane = threadIdx.x & 31;
    if (w >= n) return;

    int beg = g_off[w], end = g_off[w + 1];
    float4 acc = make_float4(0.f, 0.f, 0.f, 0.f);
    int j = beg;
    for (; j + 4 <= end; j += 4) {
        int c0 = g_cols[j], c1 = g_cols[j + 1], c2 = g_cols[j + 2], c3 = g_cols[j + 3];
        uint2 u0 = g_nbh[c0 * 32 + lane];
        uint2 u1 = g_nbh[c1 * 32 + lane];
        uint2 u2 = g_nbh[c2 * 32 + lane];
        uint2 u3 = g_nbh[c3 * 32 + lane];
#pragma unroll
        for (int q = 0; q < 4; ++q) {
            uint2 u = (q == 0) ? u0 : (q == 1) ? u1 : (q == 2) ? u2 : u3;
            float2 a = __half22float2(*(__half2*)&u.x);
            float2 b = __half22float2(*(__half2*)&u.y);
            acc.x += a.x; acc.y += a.y; acc.z += b.x; acc.w += b.y;
        }
    }
    for (; j < end; ++j) {
        int c = g_cols[j];
        uint2 u = g_nbh[c * 32 + lane];
        float2 a = __half22float2(*(__half2*)&u.x);
        float2 b = __half22float2(*(__half2*)&u.y);
        acc.x += a.x; acc.y += a.y; acc.z += b.x; acc.w += b.y;
    }
    g_aggr[w * 32 + lane] = acc;
}

// ---------------------------------------------------------------------------
// Tensor-core GEMM (tf32 mma.sync), everything folded via K-extension:
//   A' = [aggr(128) | x(8) | s(1) | 0...]   (K = 160 in 5 chunks of 32)
//   B' = [W2 ; W1 ; v3 ; 0...]
//   out = relu(A' @ B')
// Block: 128 rows x 128 cols, 256 thr = 8 warps (4M x 2N), warp = 32x64.
// ---------------------------------------------------------------------------
#define AS_STRIDE 36
#define BS_STRIDE 132

__global__ void __launch_bounds__(256, 2)
mma_fused_kernel(const float* __restrict__ x,
                 const float* __restrict__ W1,
                 const float* __restrict__ W2,
                 float* __restrict__ out, int n) {
    __shared__ unsigned As[128 * AS_STRIDE];
    __shared__ unsigned Bs[32 * BS_STRIDE];

    const int t    = threadIdx.x;
    const int lane = t & 31;
    const int w    = t >> 5;
    const int wr0  = (w >> 1) * 32;   // warp M origin
    const int wc0  = (w & 1) * 64;    // warp N origin
    const int gid  = lane >> 2;       // groupID
    const int tig  = lane & 3;        // threadID in group
    const int rbase = blockIdx.x * 128;

    float acc[2][8][4];
#pragma unroll
    for (int mi = 0; mi < 2; ++mi)
#pragma unroll
        for (int ni = 0; ni < 8; ++ni)
#pragma unroll
            for (int q = 0; q < 4; ++q) acc[mi][ni][q] = 0.f;

    for (int chunk = 0; chunk < 5; ++chunk) {
        __syncthreads();
        if (chunk < 4) {
            // As: aggr rows, k-slice [32*chunk, +32)
            for (int i = t; i < 128 * 8; i += 256) {
                int row = i >> 3, q = i & 7;
                int r = rbase + row;
                float4 v = (r < n) ? g_aggr[r * 32 + chunk * 8 + q]
                                   : make_float4(0.f, 0.f, 0.f, 0.f);
                unsigned* p = &As[row * AS_STRIDE + 4 * q];
                p[0] = f2tf32(v.x); p[1] = f2tf32(v.y);
                p[2] = f2tf32(v.z); p[3] = f2tf32(v.w);
            }
            // Bs: W2 rows [32*chunk, +32)
            for (int i = t; i < 32 * 32; i += 256) {
                int kk = i >> 5, q = i & 31;
                float4 v = ((const float4*)W2)[(chunk * 32 + kk) * 32 + q];
                unsigned* p = &Bs[kk * BS_STRIDE + 4 * q];
                p[0] = f2tf32(v.x); p[1] = f2tf32(v.y);
                p[2] = f2tf32(v.z); p[3] = f2tf32(v.w);
            }
        } else {
            // As: [x(8) | s(1) | zeros]
            for (int i = t; i < 128 * 16; i += 256) {
                int row = i >> 4, kk = i & 15;
                int r = rbase + row;
                float v = 0.f;
                if (r < n) {
                    if (kk < 8)       v = x[r * 8 + kk];
                    else if (kk == 8) v = g_s[r];
                }
                As[row * AS_STRIDE + kk] = f2tf32(v);
            }
            // Bs: [W1(8) ; v3(1) ; zeros]
            for (int i = t; i < 16 * 128; i += 256) {
                int kk = i >> 7, col = i & 127;
                float v = 0.f;
                if (kk < 8)       v = W1[kk * H + col];
                else if (kk == 8) v = ((const float*)g_v3)[col];
                Bs[kk * BS_STRIDE + col] = f2tf32(v);
            }
        }
        __syncthreads();

        const int ksteps = (chunk < 4) ? 4 : 2;
        for (int ks = 0; ks < ksteps; ++ks) {
            const int k0 = ks * 8;
            unsigned a[2][4], b[8][2];
#pragma unroll
            for (int mi = 0; mi < 2; ++mi) {
                int row = wr0 + mi * 16 + gid;
                a[mi][0] = As[row * AS_STRIDE + k0 + tig];
                a[mi][1] = As[(row + 8) * AS_STRIDE + k0 + tig];
                a[mi][2] = As[row * AS_STRIDE + k0 + tig + 4];
                a[mi][3] = As[(row + 8) * AS_STRIDE + k0 + tig + 4];
            }
#pragma unroll
            for (int ni = 0; ni < 8; ++ni) {
                int col = wc0 + ni * 8 + gid;
                b[ni][0] = Bs[(k0 + tig) * BS_STRIDE + col];
                b[ni][1] = Bs[(k0 + tig + 4) * BS_STRIDE + col];
            }
#pragma unroll
            for (int mi = 0; mi < 2; ++mi)
#pragma unroll
                for (int ni = 0; ni < 8; ++ni)
                    mma_tf32(acc[mi][ni], a[mi], b[ni]);
        }
    }

    // epilogue: relu + store
#pragma unroll
    for (int mi = 0; mi < 2; ++mi) {
#pragma unroll
        for (int half = 0; half < 2; ++half) {
            int r = rbase + wr0 + mi * 16 + gid + half * 8;
            if (r >= n) continue;
#pragma unroll
            for (int ni = 0; ni < 8; ++ni) {
                int col = wc0 + ni * 8 + 2 * tig;
                float v0 = acc[mi][ni][half * 2 + 0];
                float v1 = acc[mi][ni][half * 2 + 1];
                v0 = v0 > 0.f ? v0 : 0.f;
                v1 = v1 > 0.f ? v1 : 0.f;
                ((float2*)out)[r * 64 + (col >> 1)] = make_float2(v0, v1);
            }
        }
    }
}

// ---------------------------------------------------------------------------
extern "C" void kernel_launch(void* const* d_in, const int* in_sizes, int n_in,
                              void* d_out, int out_size) {
    const float* x   = (const float*)d_in[0];
    const void*  ei  = d_in[1];                 // int32 or int64 (device-detected)
    const float* ea  = (const float*)d_in[2];
    const float* nb  = (const float*)d_in[3];
    const float* W1  = (const float*)d_in[4];
    const float* W2  = (const float*)d_in[5];
    const float* W3  = (const float*)d_in[6];
    const float* W4  = (const float*)d_in[7];
    float* out = (float*)d_out;

    const int n   = in_sizes[0] / 8;   // 50000
    const int e   = in_sizes[2];       // 800000
    const int n4  = (n + 3) / 4;       // 12500
    const int nbs = (n4 + 255) / 256;  // 49 scan chunks
    const int ntiles = (n + 127) / 128;

    prep_kernel<<<(n * 32 + 255) / 256, 256>>>(nb, W4, W3, n);
    hist_kernel<<<(e + 255) / 256, 256>>>(ei, ea, e, n);
    scan_kernel<<<nbs, 256>>>(n, n4, nbs);
    fill_kernel<<<(e + 255) / 256, 256>>>(ei, e, n);
    aggr_kernel<<<(n * 32 + 255) / 256, 256>>>(n);
    mma_fused_kernel<<<ntiles, 256>>>(x, W1, W2, out, n);
}

// round 13
// speedup vs baseline: 1.0528x; 1.0026x over previous
#include <cuda_runtime.h>
#include <cuda_fp16.h>
#include <cstdint>

#define NMAX 50000
#define EMAX 800000
#define H 128

// ---------------- scratch (__device__ globals) ------------------------------
__device__ float4 g_aggr[NMAX * (H / 4)];  // segment-sum of nb rows (tf32 bits)
__device__ uint2  g_nbh[NMAX * 32];        // node_embedding as fp16 (256B/row)
__device__ float  g_s[NMAX];               // per-node sum of edge_attr
__device__ float4 g_v3[H / 4];             // relu(W4) @ W3
__device__ int    g_cnt[NMAX + 4];         // degree counts (padded to int4)
__device__ int    g_off[NMAX + 1];         // CSR row offsets
__device__ int    g_rank[EMAX];            // per-edge rank within its row
__device__ int    g_cols[EMAX];            // CSR column indices

// ---------------------------------------------------------------------------
__device__ __forceinline__ unsigned f2tf32(float f) {
    unsigned u;
    asm("cvt.rna.tf32.f32 %0, %1;" : "=r"(u) : "f"(f));
    return u;
}

__device__ __forceinline__ void mma_tf32(float* c, const unsigned* a,
                                         const unsigned* b) {
    asm volatile(
        "mma.sync.aligned.m16n8k8.row.col.f32.tf32.tf32.f32 "
        "{%0,%1,%2,%3}, {%4,%5,%6,%7}, {%8,%9}, {%0,%1,%2,%3};"
        : "+f"(c[0]), "+f"(c[1]), "+f"(c[2]), "+f"(c[3])
        : "r"(a[0]), "r"(a[1]), "r"(a[2]), "r"(a[3]), "r"(b[0]), "r"(b[1]));
}

__device__ __forceinline__ bool ei_is64(const void* ei) {
    const int* p32 = (const int*)ei;
    return (p32[1] | p32[3] | p32[5] | p32[7]) == 0;  // int64 => odd words 0
}

// ---------------------------------------------------------------------------
// Zero cnt/s + v3 = relu(W4)@W3 (block 0).
// ---------------------------------------------------------------------------
__global__ void zero_kernel(const float* __restrict__ W4,
                            const float* __restrict__ W3, int n) {
    int i = blockIdx.x * blockDim.x + threadIdx.x;
    int npad = (n + 3) & ~3;
    if (i < npad) g_cnt[i] = 0;
    if (i < n) g_s[i] = 0.f;
    if (blockIdx.x == 0 && threadIdx.x < H) {
        int j = threadIdx.x;
        float acc = 0.f;
#pragma unroll 8
        for (int c = 0; c < H; ++c) {
            float w = W4[c];
            w = w > 0.f ? w : 0.f;
            acc += w * W3[c * H + j];
        }
        ((float*)g_v3)[j] = acc;
    }
}

// ---------------------------------------------------------------------------
// Histogram: 2 edges/thread, row half only. rank = atomic return value.
// ---------------------------------------------------------------------------
__global__ void hist_kernel(const void* __restrict__ ei,
                            const float* __restrict__ ea, int e, int n) {
    int i2 = blockIdx.x * blockDim.x + threadIdx.x;
    int i  = i2 * 2;
    if (i >= e) return;
    bool is64 = ei_is64(ei);
    bool has1 = (i + 1 < e);

    int r0, r1 = 0;
    if (is64) {
        if (has1) {
            longlong2 v = ((const longlong2*)ei)[i2];
            r0 = (int)v.x; r1 = (int)v.y;
        } else r0 = (int)((const long long*)ei)[i];
    } else {
        if (has1) {
            int2 v = ((const int2*)ei)[i2];
            r0 = v.x; r1 = v.y;
        } else r0 = ((const int*)ei)[i];
    }
    float e0, e1 = 0.f;
    if (has1) { float2 ev = ((const float2*)ea)[i2]; e0 = ev.x; e1 = ev.y; }
    else e0 = ea[i];

    int k0 = 0, k1 = 0;
    if ((unsigned)r0 < (unsigned)n) {
        k0 = atomicAdd(&g_cnt[r0], 1);
        atomicAdd(&g_s[r0], e0);
    }
    if (has1 && (unsigned)r1 < (unsigned)n) {
        k1 = atomicAdd(&g_cnt[r1], 1);
        atomicAdd(&g_s[r1], e1);
    }
    if (has1) ((int2*)g_rank)[i2] = make_int2(k0, k1);
    else g_rank[i] = k0;
}

// ---------------------------------------------------------------------------
// Scan (blocks < nbs) + fp16 conversion of nb (all blocks).
// ---------------------------------------------------------------------------
__global__ void scan_conv_kernel(const float* __restrict__ nb,
                                 int n, int n4, int nbs) {
    __shared__ int red[8];
    __shared__ int ts[256];
    __shared__ int sbase;
    int t = threadIdx.x;
    int b = blockIdx.x;

    // convert slice (all blocks)
    int ci = b * 256 + t;
    if (ci < n * 32) {
        float4 v = ((const float4*)nb)[ci];
        __half2 h0 = __floats2half2_rn(v.x, v.y);
        __half2 h1 = __floats2half2_rn(v.z, v.w);
        uint2 u;
        u.x = *(unsigned*)&h0;
        u.y = *(unsigned*)&h1;
        g_nbh[ci] = u;
    }

    if (b >= nbs) return;
    int lane = t & 31, wid = t >> 5;

    int s = 0;
    int lim = b * 256;   // int4 units
    for (int i = t; i < lim; i += 256) {
        int4 v = ((const int4*)g_cnt)[i];
        s += v.x + v.y + v.z + v.w;
    }
#pragma unroll
    for (int o = 16; o > 0; o >>= 1) s += __shfl_down_sync(0xffffffffu, s, o);
    if (lane == 0) red[wid] = s;
    __syncthreads();
    if (t == 0) {
        int a = 0;
#pragma unroll
        for (int k = 0; k < 8; ++k) a += red[k];
        sbase = a;
    }
    __syncthreads();
    int base = sbase;

    int i = b * 256 + t;
    int4 v = (i < n4) ? ((const int4*)g_cnt)[i] : make_int4(0, 0, 0, 0);
    int tot = v.x + v.y + v.z + v.w;
    ts[t] = tot;
    __syncthreads();
#pragma unroll
    for (int d = 1; d < 256; d <<= 1) {
        int xv = (t >= d) ? ts[t - d] : 0;
        __syncthreads();
        ts[t] += xv;
        __syncthreads();
    }
    if (i < n4) {
        int o0 = base + ts[t] - tot;
        int o1 = o0 + v.x, o2 = o1 + v.y, o3 = o2 + v.z;
        ((int4*)g_off)[i] = make_int4(o0, o1, o2, o3);
    }
    if (b == nbs - 1 && t == 255) g_off[n] = base + ts[255];
}

// ---------------------------------------------------------------------------
// Fill: 2 edges/thread, atomic-free — position = off[r] + rank[i].
// ---------------------------------------------------------------------------
__global__ void fill_kernel(const void* __restrict__ ei, int e, int n) {
    int i2 = blockIdx.x * blockDim.x + threadIdx.x;
    int i  = i2 * 2;
    if (i >= e) return;
    bool is64 = ei_is64(ei);
    bool has1 = (i + 1 < e);

    int r0, r1 = 0, c0, c1 = 0;
    if (is64) {
        const long long* p64 = (const long long*)ei;
        if (has1) {
            longlong2 rv = ((const longlong2*)ei)[i2];
            longlong2 cv = ((const longlong2*)(p64 + e))[i2];
            r0 = (int)rv.x; r1 = (int)rv.y;
            c0 = (int)cv.x; c1 = (int)cv.y;
        } else { r0 = (int)p64[i]; c0 = (int)p64[e + i]; }
    } else {
        const int* p32 = (const int*)ei;
        if (has1) {
            int2 rv = ((const int2*)ei)[i2];
            int2 cv = ((const int2*)(p32 + e))[i2];
            r0 = rv.x; r1 = rv.y; c0 = cv.x; c1 = cv.y;
        } else { r0 = p32[i]; c0 = p32[e + i]; }
    }
    int2 rk = has1 ? ((const int2*)g_rank)[i2] : make_int2(g_rank[i], 0);

    if ((unsigned)r0 < (unsigned)n && (unsigned)c0 < (unsigned)n)
        g_cols[g_off[r0] + rk.x] = c0;
    if (has1 && (unsigned)r1 < (unsigned)n && (unsigned)c1 < (unsigned)n)
        g_cols[g_off[r1] + rk.y] = c1;
}

// ---------------------------------------------------------------------------
// Aggregate: warp per row, fp16 gathers (8-deep MLP), fp32 acc, tf32 output.
// ---------------------------------------------------------------------------
__global__ void aggr_kernel(int n) {
    int w    = (blockIdx.x * blockDim.x + threadIdx.x) >> 5;
    int lane = threadIdx.x & 31;
    if (w >= n) return;

    int beg = g_off[w], end = g_off[w + 1];
    float4 acc = make_float4(0.f, 0.f, 0.f, 0.f);
    int j = beg;
    for (; j + 8 <= end; j += 8) {
        int cc[8];
#pragma unroll
        for (int q = 0; q < 8; ++q) cc[q] = g_cols[j + q];
        uint2 u[8];
#pragma unroll
        for (int q = 0; q < 8; ++q) u[q] = g_nbh[cc[q] * 32 + lane];
#pragma unroll
        for (int q = 0; q < 8; ++q) {
            float2 a = __half22float2(*(__half2*)&u[q].x);
            float2 b = __half22float2(*(__half2*)&u[q].y);
            acc.x += a.x; acc.y += a.y; acc.z += b.x; acc.w += b.y;
        }
    }
    for (; j < end; ++j) {
        uint2 u = g_nbh[g_cols[j] * 32 + lane];
        float2 a = __half22float2(*(__half2*)&u.x);
        float2 b = __half22float2(*(__half2*)&u.y);
        acc.x += a.x; acc.y += a.y; acc.z += b.x; acc.w += b.y;
    }
    *(uint4*)&g_aggr[w * 32 + lane] =
        make_uint4(f2tf32(acc.x), f2tf32(acc.y), f2tf32(acc.z), f2tf32(acc.w));
}

// ---------------------------------------------------------------------------
// Tensor-core GEMM (tf32 mma.sync), K-extension folding:
//   A' = [aggr(128) | x(8) | s(1) | 0...]  (5 chunks of 32), B' = [W2;W1;v3].
//   out = relu(A' @ B')
// ---------------------------------------------------------------------------
#define AS_STRIDE 36
#define BS_STRIDE 132

__global__ void __launch_bounds__(256, 2)
mma_fused_kernel(const float* __restrict__ x,
                 const float* __restrict__ W1,
                 const float* __restrict__ W2,
                 float* __restrict__ out, int n) {
    __shared__ unsigned As[128 * AS_STRIDE];
    __shared__ unsigned Bs[32 * BS_STRIDE];

    const int t    = threadIdx.x;
    const int lane = t & 31;
    const int w    = t >> 5;
    const int wr0  = (w >> 1) * 32;
    const int wc0  = (w & 1) * 64;
    const int gid  = lane >> 2;
    const int tig  = lane & 3;
    const int rbase = blockIdx.x * 128;

    float acc[2][8][4];
#pragma unroll
    for (int mi = 0; mi < 2; ++mi)
#pragma unroll
        for (int ni = 0; ni < 8; ++ni)
#pragma unroll
            for (int q = 0; q < 4; ++q) acc[mi][ni][q] = 0.f;

    for (int chunk = 0; chunk < 5; ++chunk) {
        __syncthreads();
        if (chunk < 4) {
            // As: aggr rows (already tf32 bits) — raw uint4 copy
            for (int i = t; i < 128 * 8; i += 256) {
                int row = i >> 3, q = i & 7;
                int r = rbase + row;
                uint4 v = (r < n) ? *(const uint4*)&g_aggr[r * 32 + chunk * 8 + q]
                                  : make_uint4(0u, 0u, 0u, 0u);
                *(uint4*)&As[row * AS_STRIDE + 4 * q] = v;
            }
            // Bs: W2 rows [32*chunk, +32)
            for (int i = t; i < 32 * 32; i += 256) {
                int kk = i >> 5, q = i & 31;
                float4 v = ((const float4*)W2)[(chunk * 32 + kk) * 32 + q];
                *(uint4*)&Bs[kk * BS_STRIDE + 4 * q] =
                    make_uint4(f2tf32(v.x), f2tf32(v.y), f2tf32(v.z), f2tf32(v.w));
            }
        } else {
            // As: [x(8) | s(1) | zeros]
            for (int i = t; i < 128 * 16; i += 256) {
                int row = i >> 4, kk = i & 15;
                int r = rbase + row;
                float v = 0.f;
                if (r < n) {
                    if (kk < 8)       v = x[r * 8 + kk];
                    else if (kk == 8) v = g_s[r];
                }
                As[row * AS_STRIDE + kk] = f2tf32(v);
            }
            // Bs: [W1(8) ; v3(1) ; zeros]
            for (int i = t; i < 16 * 128; i += 256) {
                int kk = i >> 7, col = i & 127;
                float v = 0.f;
                if (kk < 8)       v = W1[kk * H + col];
                else if (kk == 8) v = ((const float*)g_v3)[col];
                Bs[kk * BS_STRIDE + col] = f2tf32(v);
            }
        }
        __syncthreads();

        const int ksteps = (chunk < 4) ? 4 : 2;
        for (int ks = 0; ks < ksteps; ++ks) {
            const int k0 = ks * 8;
            unsigned a[2][4], b[8][2];
#pragma unroll
            for (int mi = 0; mi < 2; ++mi) {
                int row = wr0 + mi * 16 + gid;
                a[mi][0] = As[row * AS_STRIDE + k0 + tig];
                a[mi][1] = As[(row + 8) * AS_STRIDE + k0 + tig];
                a[mi][2] = As[row * AS_STRIDE + k0 + tig + 4];
                a[mi][3] = As[(row + 8) * AS_STRIDE + k0 + tig + 4];
            }
#pragma unroll
            for (int ni = 0; ni < 8; ++ni) {
                int col = wc0 + ni * 8 + gid;
                b[ni][0] = Bs[(k0 + tig) * BS_STRIDE + col];
                b[ni][1] = Bs[(k0 + tig + 4) * BS_STRIDE + col];
            }
#pragma unroll
            for (int mi = 0; mi < 2; ++mi)
#pragma unroll
                for (int ni = 0; ni < 8; ++ni)
                    mma_tf32(acc[mi][ni], a[mi], b[ni]);
        }
    }

    // epilogue: relu + store
#pragma unroll
    for (int mi = 0; mi < 2; ++mi) {
#pragma unroll
        for (int half = 0; half < 2; ++half) {
            int r = rbase + wr0 + mi * 16 + gid + half * 8;
            if (r >= n) continue;
#pragma unroll
            for (int ni = 0; ni < 8; ++ni) {
                int col = wc0 + ni * 8 + 2 * tig;
                float v0 = acc[mi][ni][half * 2 + 0];
                float v1 = acc[mi][ni][half * 2 + 1];
                v0 = v0 > 0.f ? v0 : 0.f;
                v1 = v1 > 0.f ? v1 : 0.f;
                ((float2*)out)[r * 64 + (col >> 1)] = make_float2(v0, v1);
            }
        }
    }
}

// ---------------------------------------------------------------------------
extern "C" void kernel_launch(void* const* d_in, const int* in_sizes, int n_in,
                              void* d_out, int out_size) {
    const float* x   = (const float*)d_in[0];
    const void*  ei  = d_in[1];                 // int32 or int64 (device-detected)
    const float* ea  = (const float*)d_in[2];
    const float* nb  = (const float*)d_in[3];
    const float* W1  = (const float*)d_in[4];
    const float* W2  = (const float*)d_in[5];
    const float* W3  = (const float*)d_in[6];
    const float* W4  = (const float*)d_in[7];
    float* out = (float*)d_out;

    const int n   = in_sizes[0] / 8;   // 50000
    const int e   = in_sizes[2];       // 800000
    const int n4  = (n + 3) / 4;       // 12500
    const int nbs = (n4 + 255) / 256;  // 49 scan chunks
    const int ntiles = (n + 127) / 128;
    const int e2  = (e + 1) / 2;       // edge pairs
    const int nconv = (n * 32 + 255) / 256;  // convert blocks (>= nbs)

    zero_kernel<<<(n + 255) / 256, 256>>>(W4, W3, n);
    hist_kernel<<<(e2 + 255) / 256, 256>>>(ei, ea, e, n);
    scan_conv_kernel<<<nconv, 256>>>(nb, n, n4, nbs);
    fill_kernel<<<(e2 + 255) / 256, 256>>>(ei, e, n);
    aggr_kernel<<<(n * 32 + 255) / 256, 256>>>(n);
    mma_fused_kernel<<<ntiles, 256>>>(x, W1, W2, out, n);
}